// round 14
// baseline (speedup 1.0000x reference)
#include <cuda_runtime.h>
#include <math.h>

// Problem constants
#define NT   8192
#define DM   1024
#define FF   32
#define NE   8
#define NPE  8
#define DFE  128
#define DRH  256
#define DEH  512
#define KIN  1152          // DM + DFE
#define NSLOT (NT * 2)

// ---------------- scratch (static device globals; no allocation) ----------------
// EXACT R4/R13 layout (proven delta=0 on the allocation guard).
__device__ float g_fs[NT * DFE];        // 4 MB   router stage-feature embedding
__device__ float g_hr[NT * DRH];        // 8 MB   router hidden
__device__ float g_fe[NSLOT * DFE];     // 16 MB  per-slot expert feature embedding
__device__ float g_h1[NSLOT * DEH];     // 32 MB  expert hidden
__device__ float g_os[NSLOT * DM];      // 64 MB  per-slot expert output
__device__ float g_w[NSLOT];            // gate weights per slot
__device__ int   g_eid[NSLOT];          // expert id per slot
__device__ int   g_cnt[NE];             // per-expert token counts
__device__ int   g_list[NE * NT];       // per-expert slot lists

__device__ __forceinline__ float gelu_f(float x) {
    // jax.nn.gelu default (approximate=True, tanh form)
    return 0.5f * x * (1.0f + tanhf(0.7978845608028654f * (x + 0.044715f * x * x * x)));
}

// ---- packed fp32x2 helpers (FMA pipe, not tensor) ----
__device__ __forceinline__ unsigned long long pk2(float lo, float hi) {
    unsigned long long r;
    asm("mov.b64 %0, {%1, %2};"
        : "=l"(r) : "r"(__float_as_uint(lo)), "r"(__float_as_uint(hi)));
    return r;
}
__device__ __forceinline__ void upk2(float& lo, float& hi, unsigned long long v) {
    unsigned int l_, h_;
    asm("mov.b64 {%0, %1}, %2;" : "=r"(l_), "=r"(h_) : "l"(v));
    lo = __uint_as_float(l_); hi = __uint_as_float(h_);
}
__device__ __forceinline__ void ffma2(unsigned long long& d,
                                      unsigned long long a, unsigned long long b) {
    asm("fma.rn.f32x2 %0, %1, %2, %0;" : "+l"(d) : "l"(a), "l"(b));
}

__global__ void zero_cnt_k() {
    if (threadIdx.x < NE) g_cnt[threadIdx.x] = 0;
}

// fs = feat[:, stage_idx] @ Wfs + bfs       [NT, DFE]
__global__ void fs_k(const float* __restrict__ feat, const int* __restrict__ stage_idx,
                     const float* __restrict__ Wfs, const float* __restrict__ bfs) {
    int n = blockIdx.x, t = threadIdx.x;       // 128 threads
    __shared__ float f[FF];
    if (t < FF) f[t] = feat[n * FF + stage_idx[t]];
    __syncthreads();
    float acc = bfs[t];
#pragma unroll
    for (int j = 0; j < FF; j++) acc += f[j] * Wfs[j * DFE + t];
    g_fs[n * DFE + t] = acc;
}

// logits = g_hr @ Wr2 + br2 ; top-2 softmax ; build per-expert lists
__global__ void router_topk_k(const float* __restrict__ Wr2, const float* __restrict__ br2) {
    int warp = threadIdx.x >> 5, lane = threadIdx.x & 31;
    int n = blockIdx.x * 8 + warp;
    if (n >= NT) return;
    const float* hr = g_hr + (long)n * DRH;
    float acc[NE];
#pragma unroll
    for (int e = 0; e < NE; e++) acc[e] = 0.f;
    for (int k = lane; k < DRH; k += 32) {
        float h = hr[k];
        const float* w = Wr2 + k * NE;
#pragma unroll
        for (int e = 0; e < NE; e++) acc[e] += h * w[e];
    }
#pragma unroll
    for (int off = 16; off > 0; off >>= 1)
#pragma unroll
        for (int e = 0; e < NE; e++) acc[e] += __shfl_down_sync(0xffffffffu, acc[e], off);
    if (lane == 0) {
        float lg[NE];
#pragma unroll
        for (int e = 0; e < NE; e++) lg[e] = acc[e] + br2[e];   // TEMP = 1
        int i0 = 0;
#pragma unroll
        for (int e = 1; e < NE; e++) if (lg[e] > lg[i0]) i0 = e;
        int i1 = (i0 == 0) ? 1 : 0;
#pragma unroll
        for (int e = 0; e < NE; e++) if (e != i0 && lg[e] > lg[i1]) i1 = e;
        float ex = expf(lg[i1] - lg[i0]);
        float inv = 1.0f / (1.0f + ex);
        g_eid[2 * n] = i0;  g_eid[2 * n + 1] = i1;
        g_w[2 * n] = inv;   g_w[2 * n + 1] = ex * inv;
        int p0 = atomicAdd(&g_cnt[i0], 1); g_list[i0 * NT + p0] = 2 * n;
        int p1 = atomicAdd(&g_cnt[i1], 1); g_list[i1 * NT + p1] = 2 * n + 1;
    }
}

// fe[slot] = feat[n, expert_idx[e,:]] @ Wfe[e] + bfe[e]      (one block per slot)
__global__ void fe_k(const float* __restrict__ feat, const int* __restrict__ expert_idx,
                     const float* __restrict__ Wfe, const float* __restrict__ bfe) {
    int s = blockIdx.x, t = threadIdx.x;       // 128 threads
    int n = s >> 1;
    int e = g_eid[s];
    __shared__ float f[NPE];
    if (t < NPE) f[t] = feat[n * FF + expert_idx[e * NPE + t]];
    __syncthreads();
    float acc = bfe[e * DFE + t];
#pragma unroll
    for (int j = 0; j < NPE; j++) acc += f[j] * Wfe[(e * NPE + j) * DFE + t];
    g_fe[s * DFE + t] = acc;
}

// -------- tiled fp32 GEMM, packed FFMA2 with PRE-DUPLICATED A tile --------
// 128x128x16 tiles, 256 threads. A stored in smem as u64 {v,v}; B read as
// natural n-adjacent u64 pairs. Inner loop: 6x LDS.128 + 32x FFMA2, zero movs.
// MODE 1: router  — A row m: [hidden | g_fs[m]],        C = g_hr, K=1152, N=256
// MODE 2: expert1 — s=rows[m]: [hidden[s>>1] | g_fe[s]], C = g_h1, K=1152, N=512
// MODE 3: expert2 — s=rows[m]: g_h1[s],                  C = g_os, K=512,  N=1024
template<int MODE, bool ACT>
__global__ void __launch_bounds__(256)
gemm_k(const float* __restrict__ A1,      // hidden (MODE 1/2); unused MODE 3
       const float* __restrict__ B, const float* __restrict__ bias,
       int M, int Nn, int K, int K1,
       int lda1, int ldc, long sB, int sBias) {
    int e = blockIdx.z;
    const int* rows = (MODE >= 2) ? (g_list + e * NT) : nullptr;
    if (MODE >= 2) M = g_cnt[e];
    int m0 = blockIdx.y * 128;
    if (m0 >= M) return;
    const float* Bp = B + (long)e * sB;
    const float* bp = bias + (long)e * sBias;
    int n0 = blockIdx.x * 128;

    // bind scratch operands from device globals
    const float* A2 = (MODE == 1) ? g_fs : g_fe;               // second concat segment
    float* C        = (MODE == 1) ? g_hr : (MODE == 2 ? g_h1 : g_os);

    __shared__ unsigned long long As2[16][130];  // duplicated {v,v}; stride even => 16B-aligned rows
    __shared__ float Bs[16][128];

    int tid = threadIdx.x;
    int lm = tid >> 1, lk = (tid & 1) * 8;          // A-load: row lm, 8 cols from lk
    int gm = m0 + lm;
    bool mval = gm < M;
    const float* rA1 = A1;
    const float* rA2 = A2;
    if (mval) {
        if (MODE == 1)      { rA1 = A1 + (long)gm * lda1;        rA2 = A2 + (long)gm * DFE; }
        else if (MODE == 2) { int s = rows[gm];
                              rA1 = A1 + (long)(s >> 1) * lda1;  rA2 = A2 + (long)s * DFE; }
        else                { int s = rows[gm];
                              rA1 = g_h1 + (long)s * DEH; }
    }
    int lkb = tid >> 4, lnb = (tid & 15) * 8;       // B-load: row lkb, 8 cols from lnb
    int tr = tid >> 4,  tc = tid & 15;              // compute tile coords

    unsigned long long acc[8][4];                   // packed f32x2, cols n-adjacent
#pragma unroll
    for (int i = 0; i < 8; i++)
#pragma unroll
        for (int j = 0; j < 4; j++) acc[i][j] = 0ull;

    for (int k0 = 0; k0 < K; k0 += 16) {
        float4 va0 = make_float4(0.f, 0.f, 0.f, 0.f), va1 = va0;
        if (mval) {
            const float* p = ((MODE == 1 || MODE == 2) && k0 >= K1) ? (rA2 + (k0 - K1))
                                                                    : (rA1 + k0);
            va0 = *(const float4*)(p + lk);
            va1 = *(const float4*)(p + lk + 4);
        }
        As2[lk + 0][lm] = pk2(va0.x, va0.x);
        As2[lk + 1][lm] = pk2(va0.y, va0.y);
        As2[lk + 2][lm] = pk2(va0.z, va0.z);
        As2[lk + 3][lm] = pk2(va0.w, va0.w);
        As2[lk + 4][lm] = pk2(va1.x, va1.x);
        As2[lk + 5][lm] = pk2(va1.y, va1.y);
        As2[lk + 6][lm] = pk2(va1.z, va1.z);
        As2[lk + 7][lm] = pk2(va1.w, va1.w);
        const float* pb = Bp + (long)(k0 + lkb) * Nn + n0 + lnb;
        *(float4*)&Bs[lkb][lnb]     = *(const float4*)pb;
        *(float4*)&Bs[lkb][lnb + 4] = *(const float4*)(pb + 4);
        __syncthreads();
#pragma unroll
        for (int k = 0; k < 16; k++) {
            // A: 8 duplicated u64 (4x LDS.128)
            ulonglong2 a01 = *(const ulonglong2*)&As2[k][tr * 4];
            ulonglong2 a23 = *(const ulonglong2*)&As2[k][tr * 4 + 2];
            ulonglong2 a45 = *(const ulonglong2*)&As2[k][64 + tr * 4];
            ulonglong2 a67 = *(const ulonglong2*)&As2[k][64 + tr * 4 + 2];
            // B: 4 natural pairs (2x LDS.128 reinterpreted)
            ulonglong2 b01 = *(const ulonglong2*)&Bs[k][tc * 4];
            ulonglong2 b23 = *(const ulonglong2*)&Bs[k][64 + tc * 4];
            ffma2(acc[0][0], a01.x, b01.x); ffma2(acc[0][1], a01.x, b01.y);
            ffma2(acc[0][2], a01.x, b23.x); ffma2(acc[0][3], a01.x, b23.y);
            ffma2(acc[1][0], a01.y, b01.x); ffma2(acc[1][1], a01.y, b01.y);
            ffma2(acc[1][2], a01.y, b23.x); ffma2(acc[1][3], a01.y, b23.y);
            ffma2(acc[2][0], a23.x, b01.x); ffma2(acc[2][1], a23.x, b01.y);
            ffma2(acc[2][2], a23.x, b23.x); ffma2(acc[2][3], a23.x, b23.y);
            ffma2(acc[3][0], a23.y, b01.x); ffma2(acc[3][1], a23.y, b01.y);
            ffma2(acc[3][2], a23.y, b23.x); ffma2(acc[3][3], a23.y, b23.y);
            ffma2(acc[4][0], a45.x, b01.x); ffma2(acc[4][1], a45.x, b01.y);
            ffma2(acc[4][2], a45.x, b23.x); ffma2(acc[4][3], a45.x, b23.y);
            ffma2(acc[5][0], a45.y, b01.x); ffma2(acc[5][1], a45.y, b01.y);
            ffma2(acc[5][2], a45.y, b23.x); ffma2(acc[5][3], a45.y, b23.y);
            ffma2(acc[6][0], a67.x, b01.x); ffma2(acc[6][1], a67.x, b01.y);
            ffma2(acc[6][2], a67.x, b23.x); ffma2(acc[6][3], a67.x, b23.y);
            ffma2(acc[7][0], a67.y, b01.x); ffma2(acc[7][1], a67.y, b01.y);
            ffma2(acc[7][2], a67.y, b23.x); ffma2(acc[7][3], a67.y, b23.y);
        }
        __syncthreads();
    }

#pragma unroll
    for (int i = 0; i < 8; i++) {
        int mi = m0 + ((i < 4) ? (tr * 4 + i) : (64 + tr * 4 + (i - 4)));
        if (mi >= M) continue;
        int orow = (MODE >= 2) ? rows[mi] : mi;
        float* crow = C + (long)orow * ldc;
#pragma unroll
        for (int j = 0; j < 4; j++) {
            int nj = n0 + ((j < 2) ? (tc * 4 + j * 2) : (64 + tc * 4 + (j - 2) * 2));
            float v0, v1;
            upk2(v0, v1, acc[i][j]);
            v0 += bp[nj];
            v1 += bp[nj + 1];
            if (ACT) { v0 = gelu_f(v0); v1 = gelu_f(v1); }
            crow[nj]     = v0;
            crow[nj + 1] = v1;
        }
    }
}

// out = hidden + w0 * os[2n] + w1 * os[2n+1]
__global__ void combine_k(const float* __restrict__ hidden, float* __restrict__ out) {
    int n = blockIdx.x;
    float w0 = g_w[2 * n], w1 = g_w[2 * n + 1];
    const float* o0 = g_os + (long)(2 * n) * DM;
    const float* o1 = o0 + DM;
    const float* h  = hidden + (long)n * DM;
    float* o = out + (long)n * DM;
    for (int i = threadIdx.x; i < DM; i += blockDim.x)
        o[i] = h[i] + w0 * o0[i] + w1 * o1[i];
}

extern "C" void kernel_launch(void* const* d_in, const int* in_sizes, int n_in,
                              void* d_out, int out_size) {
    const float* hidden = (const float*)d_in[0];
    const float* feat   = (const float*)d_in[1];
    const float* Wfs    = (const float*)d_in[2];
    const float* bfs    = (const float*)d_in[3];
    const float* Wr1    = (const float*)d_in[4];
    const float* br1    = (const float*)d_in[5];
    const float* Wr2    = (const float*)d_in[6];
    const float* br2    = (const float*)d_in[7];
    const float* Wfe    = (const float*)d_in[8];
    const float* bfe    = (const float*)d_in[9];
    const float* We1    = (const float*)d_in[10];
    const float* be1    = (const float*)d_in[11];
    const float* We2    = (const float*)d_in[12];
    const float* be2    = (const float*)d_in[13];
    const int* expert_idx = (const int*)d_in[14];
    const int* stage_idx  = (const int*)d_in[15];
    float* out = (float*)d_out;

    zero_cnt_k<<<1, 32>>>();
    // router feature embedding
    fs_k<<<NT, DFE>>>(feat, stage_idx, Wfs, bfs);
    // router hidden: gelu([hidden|fs] @ Wr1 + br1) -> g_hr   [NT, DRH]
    gemm_k<1, true><<<dim3(DRH / 128, NT / 128, 1), 256>>>(
        hidden, Wr1, br1, NT, DRH, KIN, DM, DM, DRH, 0, 0);
    // logits + top-2 + lists
    router_topk_k<<<NT / 8, 256>>>(Wr2, br2);
    // per-slot expert feature embedding
    fe_k<<<NSLOT, DFE>>>(feat, expert_idx, Wfe, bfe);
    // expert MLP layer 1: g_h1[s] = gelu([hidden|g_fe[s]] @ We1[e] + be1[e])
    gemm_k<2, true><<<dim3(DEH / 128, NT / 128, NE), 256>>>(
        hidden, We1, be1, 0, DEH, KIN, DM, DM, DEH,
        (long)KIN * DEH, DEH);
    // expert MLP layer 2: g_os[s] = g_h1[s] @ We2[e] + be2[e]
    gemm_k<3, false><<<dim3(DM / 128, NT / 128, NE), 256>>>(
        nullptr, We2, be2, 0, DM, DEH, 0, 0, DM,
        (long)DEH * DM, DM);
    // gated residual combine
    combine_k<<<NT, 256>>>(hidden, out);
}

// round 16
// speedup vs baseline: 1.3082x; 1.3082x over previous
#include <cuda_runtime.h>
#include <math.h>

// Problem constants
#define NT   8192
#define DM   1024
#define FF   32
#define NE   8
#define NPE  8
#define DFE  128
#define DRH  256
#define DEH  512
#define KIN  1152          // DM + DFE
#define NSLOT (NT * 2)

// ---------------- scratch (static device globals; no allocation) ----------------
// EXACT R4/R13 layout (proven delta=0 on the allocation guard).
__device__ float g_fs[NT * DFE];        // 4 MB   router stage-feature embedding
__device__ float g_hr[NT * DRH];        // 8 MB   router hidden
__device__ float g_fe[NSLOT * DFE];     // 16 MB  per-slot expert feature embedding
__device__ float g_h1[NSLOT * DEH];     // 32 MB  expert hidden
__device__ float g_os[NSLOT * DM];      // 64 MB  per-slot expert output
__device__ float g_w[NSLOT];            // gate weights per slot
__device__ int   g_eid[NSLOT];          // expert id per slot
__device__ int   g_cnt[NE];             // per-expert token counts
__device__ int   g_list[NE * NT];       // per-expert slot lists

__device__ __forceinline__ float gelu_f(float x) {
    // jax.nn.gelu default (approximate=True, tanh form)
    return 0.5f * x * (1.0f + tanhf(0.7978845608028654f * (x + 0.044715f * x * x * x)));
}

// ---- packed fp32x2 helpers (FMA pipe, not tensor) ----
__device__ __forceinline__ unsigned long long pk2(float lo, float hi) {
    unsigned long long r;
    asm("mov.b64 %0, {%1, %2};"
        : "=l"(r) : "r"(__float_as_uint(lo)), "r"(__float_as_uint(hi)));
    return r;
}
__device__ __forceinline__ void upk2(float& lo, float& hi, unsigned long long v) {
    unsigned int l_, h_;
    asm("mov.b64 {%0, %1}, %2;" : "=r"(l_), "=r"(h_) : "l"(v));
    lo = __uint_as_float(l_); hi = __uint_as_float(h_);
}
__device__ __forceinline__ void ffma2(unsigned long long& d,
                                      unsigned long long a, unsigned long long b) {
    asm("fma.rn.f32x2 %0, %1, %2, %0;" : "+l"(d) : "l"(a), "l"(b));
}

__global__ void zero_cnt_k() {
    if (threadIdx.x < NE) g_cnt[threadIdx.x] = 0;
}

// fs = feat[:, stage_idx] @ Wfs + bfs       [NT, DFE]
__global__ void fs_k(const float* __restrict__ feat, const int* __restrict__ stage_idx,
                     const float* __restrict__ Wfs, const float* __restrict__ bfs) {
    int n = blockIdx.x, t = threadIdx.x;       // 128 threads
    __shared__ float f[FF];
    if (t < FF) f[t] = feat[n * FF + stage_idx[t]];
    __syncthreads();
    float acc = bfs[t];
#pragma unroll
    for (int j = 0; j < FF; j++) acc += f[j] * Wfs[j * DFE + t];
    g_fs[n * DFE + t] = acc;
}

// logits = g_hr @ Wr2 + br2 ; top-2 softmax ; build per-expert lists
__global__ void router_topk_k(const float* __restrict__ Wr2, const float* __restrict__ br2) {
    int warp = threadIdx.x >> 5, lane = threadIdx.x & 31;
    int n = blockIdx.x * 8 + warp;
    if (n >= NT) return;
    const float* hr = g_hr + (long)n * DRH;
    float acc[NE];
#pragma unroll
    for (int e = 0; e < NE; e++) acc[e] = 0.f;
    for (int k = lane; k < DRH; k += 32) {
        float h = hr[k];
        const float* w = Wr2 + k * NE;
#pragma unroll
        for (int e = 0; e < NE; e++) acc[e] += h * w[e];
    }
#pragma unroll
    for (int off = 16; off > 0; off >>= 1)
#pragma unroll
        for (int e = 0; e < NE; e++) acc[e] += __shfl_down_sync(0xffffffffu, acc[e], off);
    if (lane == 0) {
        float lg[NE];
#pragma unroll
        for (int e = 0; e < NE; e++) lg[e] = acc[e] + br2[e];   // TEMP = 1
        int i0 = 0;
#pragma unroll
        for (int e = 1; e < NE; e++) if (lg[e] > lg[i0]) i0 = e;
        int i1 = (i0 == 0) ? 1 : 0;
#pragma unroll
        for (int e = 0; e < NE; e++) if (e != i0 && lg[e] > lg[i1]) i1 = e;
        float ex = expf(lg[i1] - lg[i0]);
        float inv = 1.0f / (1.0f + ex);
        g_eid[2 * n] = i0;  g_eid[2 * n + 1] = i1;
        g_w[2 * n] = inv;   g_w[2 * n + 1] = ex * inv;
        int p0 = atomicAdd(&g_cnt[i0], 1); g_list[i0 * NT + p0] = 2 * n;
        int p1 = atomicAdd(&g_cnt[i1], 1); g_list[i1 * NT + p1] = 2 * n + 1;
    }
}

// fe[slot] = feat[n, expert_idx[e,:]] @ Wfe[e] + bfe[e]      (one block per slot)
__global__ void fe_k(const float* __restrict__ feat, const int* __restrict__ expert_idx,
                     const float* __restrict__ Wfe, const float* __restrict__ bfe) {
    int s = blockIdx.x, t = threadIdx.x;       // 128 threads
    int n = s >> 1;
    int e = g_eid[s];
    __shared__ float f[NPE];
    if (t < NPE) f[t] = feat[n * FF + expert_idx[e * NPE + t]];
    __syncthreads();
    float acc = bfe[e * DFE + t];
#pragma unroll
    for (int j = 0; j < NPE; j++) acc += f[j] * Wfe[(e * NPE + j) * DFE + t];
    g_fe[s * DFE + t] = acc;
}

// -------- tiled fp32 GEMM, FFMA2 inner loop (R13) + DOUBLE-BUFFERED smem --------
// 128x128x16 tiles, 256 threads, one __syncthreads per k-tile; next tile's LDGs
// are issued before computing the current tile so global latency overlaps FMA work.
// MODE 1: router  — A row m: [hidden | g_fs[m]],        C = g_hr, K=1152, N=256
// MODE 2: expert1 — s=rows[m]: [hidden[s>>1] | g_fe[s]], C = g_h1, K=1152, N=512
// MODE 3: expert2 — s=rows[m]: g_h1[s],                  C = g_os, K=512,  N=1024
template<int MODE, bool ACT>
__global__ void __launch_bounds__(256)
gemm_k(const float* __restrict__ A1,      // hidden (MODE 1/2); unused MODE 3
       const float* __restrict__ B, const float* __restrict__ bias,
       int M, int Nn, int K, int K1,
       int lda1, int ldc, long sB, int sBias) {
    int e = blockIdx.z;
    const int* rows = (MODE >= 2) ? (g_list + e * NT) : nullptr;
    if (MODE >= 2) M = g_cnt[e];
    int m0 = blockIdx.y * 128;
    if (m0 >= M) return;
    const float* Bp = B + (long)e * sB;
    const float* bp = bias + (long)e * sBias;
    int n0 = blockIdx.x * 128;

    // bind scratch operands from device globals
    const float* A2 = (MODE == 1) ? g_fs : g_fe;               // second concat segment
    float* C        = (MODE == 1) ? g_hr : (MODE == 2 ? g_h1 : g_os);

    __shared__ float As[2][16][128];
    __shared__ float Bs[2][16][128];

    int tid = threadIdx.x;
    int lm = tid >> 1, lk = (tid & 1) * 8;          // A-load: row lm, 8 cols from lk
    int gm = m0 + lm;
    bool mval = gm < M;
    const float* rA1 = A1;
    const float* rA2 = A2;
    if (mval) {
        if (MODE == 1)      { rA1 = A1 + (long)gm * lda1;        rA2 = A2 + (long)gm * DFE; }
        else if (MODE == 2) { int s = rows[gm];
                              rA1 = A1 + (long)(s >> 1) * lda1;  rA2 = A2 + (long)s * DFE; }
        else                { int s = rows[gm];
                              rA1 = g_h1 + (long)s * DEH; }
    }
    int lkb = tid >> 4, lnb = (tid & 15) * 8;       // B-load: row lkb, 8 cols from lnb
    int tr = tid >> 4,  tc = tid & 15;              // compute tile coords

    unsigned long long acc[8][4];                   // packed f32x2, cols n-adjacent
#pragma unroll
    for (int i = 0; i < 8; i++)
#pragma unroll
        for (int j = 0; j < 4; j++) acc[i][j] = 0ull;

    // ---- prologue: load tile 0 into buffer 0 ----
    float4 va0 = make_float4(0.f, 0.f, 0.f, 0.f), va1 = va0;
    if (mval) {
        const float* p = ((MODE == 1 || MODE == 2) && 0 >= K1) ? rA2 : rA1;
        va0 = *(const float4*)(p + lk);
        va1 = *(const float4*)(p + lk + 4);
    }
    {
        const float* pb = Bp + (long)lkb * Nn + n0 + lnb;
        float4 vb0 = *(const float4*)pb;
        float4 vb1 = *(const float4*)(pb + 4);
        As[0][lk + 0][lm] = va0.x; As[0][lk + 1][lm] = va0.y;
        As[0][lk + 2][lm] = va0.z; As[0][lk + 3][lm] = va0.w;
        As[0][lk + 4][lm] = va1.x; As[0][lk + 5][lm] = va1.y;
        As[0][lk + 6][lm] = va1.z; As[0][lk + 7][lm] = va1.w;
        *(float4*)&Bs[0][lkb][lnb]     = vb0;
        *(float4*)&Bs[0][lkb][lnb + 4] = vb1;
    }
    __syncthreads();

    int nTiles = K / 16;
    for (int t = 0; t < nTiles; t++) {
        int buf = t & 1;
        // ---- prefetch next tile's global data (overlaps compute below) ----
        float4 pa0 = make_float4(0.f, 0.f, 0.f, 0.f), pa1 = pa0;
        float4 pb0, pb1;
        bool have_next = (t + 1 < nTiles);
        if (have_next) {
            int k0 = (t + 1) * 16;
            if (mval) {
                const float* p = ((MODE == 1 || MODE == 2) && k0 >= K1) ? (rA2 + (k0 - K1))
                                                                        : (rA1 + k0);
                pa0 = *(const float4*)(p + lk);
                pa1 = *(const float4*)(p + lk + 4);
            }
            const float* pb = Bp + (long)(k0 + lkb) * Nn + n0 + lnb;
            pb0 = *(const float4*)pb;
            pb1 = *(const float4*)(pb + 4);
        }
        // ---- compute current tile ----
#pragma unroll
        for (int k = 0; k < 16; k++) {
            float4 a0 = *(const float4*)&As[buf][k][tr * 4];
            float4 a1 = *(const float4*)&As[buf][k][64 + tr * 4];
            float4 bl = *(const float4*)&Bs[buf][k][tc * 4];
            float4 bh = *(const float4*)&Bs[buf][k][64 + tc * 4];
            unsigned long long bpk0 = pk2(bl.x, bl.y), bpk1 = pk2(bl.z, bl.w);
            unsigned long long bpk2_ = pk2(bh.x, bh.y), bpk3 = pk2(bh.z, bh.w);
            unsigned long long ad0 = pk2(a0.x, a0.x), ad1 = pk2(a0.y, a0.y);
            unsigned long long ad2 = pk2(a0.z, a0.z), ad3 = pk2(a0.w, a0.w);
            unsigned long long ad4 = pk2(a1.x, a1.x), ad5 = pk2(a1.y, a1.y);
            unsigned long long ad6 = pk2(a1.z, a1.z), ad7 = pk2(a1.w, a1.w);
            ffma2(acc[0][0], ad0, bpk0); ffma2(acc[0][1], ad0, bpk1);
            ffma2(acc[0][2], ad0, bpk2_); ffma2(acc[0][3], ad0, bpk3);
            ffma2(acc[1][0], ad1, bpk0); ffma2(acc[1][1], ad1, bpk1);
            ffma2(acc[1][2], ad1, bpk2_); ffma2(acc[1][3], ad1, bpk3);
            ffma2(acc[2][0], ad2, bpk0); ffma2(acc[2][1], ad2, bpk1);
            ffma2(acc[2][2], ad2, bpk2_); ffma2(acc[2][3], ad2, bpk3);
            ffma2(acc[3][0], ad3, bpk0); ffma2(acc[3][1], ad3, bpk1);
            ffma2(acc[3][2], ad3, bpk2_); ffma2(acc[3][3], ad3, bpk3);
            ffma2(acc[4][0], ad4, bpk0); ffma2(acc[4][1], ad4, bpk1);
            ffma2(acc[4][2], ad4, bpk2_); ffma2(acc[4][3], ad4, bpk3);
            ffma2(acc[5][0], ad5, bpk0); ffma2(acc[5][1], ad5, bpk1);
            ffma2(acc[5][2], ad5, bpk2_); ffma2(acc[5][3], ad5, bpk3);
            ffma2(acc[6][0], ad6, bpk0); ffma2(acc[6][1], ad6, bpk1);
            ffma2(acc[6][2], ad6, bpk2_); ffma2(acc[6][3], ad6, bpk3);
            ffma2(acc[7][0], ad7, bpk0); ffma2(acc[7][1], ad7, bpk1);
            ffma2(acc[7][2], ad7, bpk2_); ffma2(acc[7][3], ad7, bpk3);
        }
        // ---- store prefetched tile into the other buffer ----
        if (have_next) {
            int nbuf = buf ^ 1;
            As[nbuf][lk + 0][lm] = pa0.x; As[nbuf][lk + 1][lm] = pa0.y;
            As[nbuf][lk + 2][lm] = pa0.z; As[nbuf][lk + 3][lm] = pa0.w;
            As[nbuf][lk + 4][lm] = pa1.x; As[nbuf][lk + 5][lm] = pa1.y;
            As[nbuf][lk + 6][lm] = pa1.z; As[nbuf][lk + 7][lm] = pa1.w;
            *(float4*)&Bs[nbuf][lkb][lnb]     = pb0;
            *(float4*)&Bs[nbuf][lkb][lnb + 4] = pb1;
            __syncthreads();
        }
    }

#pragma unroll
    for (int i = 0; i < 8; i++) {
        int mi = m0 + ((i < 4) ? (tr * 4 + i) : (64 + tr * 4 + (i - 4)));
        if (mi >= M) continue;
        int orow = (MODE >= 2) ? rows[mi] : mi;
        float* crow = C + (long)orow * ldc;
#pragma unroll
        for (int j = 0; j < 4; j++) {
            int nj = n0 + ((j < 2) ? (tc * 4 + j * 2) : (64 + tc * 4 + (j - 2) * 2));
            float v0, v1;
            upk2(v0, v1, acc[i][j]);
            v0 += bp[nj];
            v1 += bp[nj + 1];
            if (ACT) { v0 = gelu_f(v0); v1 = gelu_f(v1); }
            crow[nj]     = v0;
            crow[nj + 1] = v1;
        }
    }
}

// out = hidden + w0 * os[2n] + w1 * os[2n+1]
__global__ void combine_k(const float* __restrict__ hidden, float* __restrict__ out) {
    int n = blockIdx.x;
    float w0 = g_w[2 * n], w1 = g_w[2 * n + 1];
    const float* o0 = g_os + (long)(2 * n) * DM;
    const float* o1 = o0 + DM;
    const float* h  = hidden + (long)n * DM;
    float* o = out + (long)n * DM;
    for (int i = threadIdx.x; i < DM; i += blockDim.x)
        o[i] = h[i] + w0 * o0[i] + w1 * o1[i];
}

extern "C" void kernel_launch(void* const* d_in, const int* in_sizes, int n_in,
                              void* d_out, int out_size) {
    const float* hidden = (const float*)d_in[0];
    const float* feat   = (const float*)d_in[1];
    const float* Wfs    = (const float*)d_in[2];
    const float* bfs    = (const float*)d_in[3];
    const float* Wr1    = (const float*)d_in[4];
    const float* br1    = (const float*)d_in[5];
    const float* Wr2    = (const float*)d_in[6];
    const float* br2    = (const float*)d_in[7];
    const float* Wfe    = (const float*)d_in[8];
    const float* bfe    = (const float*)d_in[9];
    const float* We1    = (const float*)d_in[10];
    const float* be1    = (const float*)d_in[11];
    const float* We2    = (const float*)d_in[12];
    const float* be2    = (const float*)d_in[13];
    const int* expert_idx = (const int*)d_in[14];
    const int* stage_idx  = (const int*)d_in[15];
    float* out = (float*)d_out;

    zero_cnt_k<<<1, 32>>>();
    // router feature embedding
    fs_k<<<NT, DFE>>>(feat, stage_idx, Wfs, bfs);
    // router hidden: gelu([hidden|fs] @ Wr1 + br1) -> g_hr   [NT, DRH]
    gemm_k<1, true><<<dim3(DRH / 128, NT / 128, 1), 256>>>(
        hidden, Wr1, br1, NT, DRH, KIN, DM, DM, DRH, 0, 0);
    // logits + top-2 + lists
    router_topk_k<<<NT / 8, 256>>>(Wr2, br2);
    // per-slot expert feature embedding
    fe_k<<<NSLOT, DFE>>>(feat, expert_idx, Wfe, bfe);
    // expert MLP layer 1: g_h1[s] = gelu([hidden|g_fe[s]] @ We1[e] + be1[e])
    gemm_k<2, true><<<dim3(DEH / 128, NT / 128, NE), 256>>>(
        hidden, We1, be1, 0, DEH, KIN, DM, DM, DEH,
        (long)KIN * DEH, DEH);
    // expert MLP layer 2: g_os[s] = g_h1[s] @ We2[e] + be2[e]
    gemm_k<3, false><<<dim3(DM / 128, NT / 128, NE), 256>>>(
        nullptr, We2, be2, 0, DM, DEH, 0, 0, DM,
        (long)DEH * DM, DM);
    // gated residual combine
    combine_k<<<NT, 256>>>(hidden, out);
}